// round 1
// baseline (speedup 1.0000x reference)
#include <cuda_runtime.h>

#define NPIX 6400      // 80*80
#define OUTP 160
#define INP  80
#define NB   16
#define NCLS 8

// Scratch (no dynamic allocation allowed)
__device__ float g_buf1[16 * 512 * 6400];   // f1, reused for f2(=Y3)
__device__ float g_buf2[16 * 256 * 6400];   // f (after conv2)
__device__ float g_A[16 * 8 * 6400];        // bilinear-weighted onehot mass on 80x80 grid
__device__ float g_cnt[16 * 8];             // class counts at 160x160

// ---------------------------------------------------------------------------
// Zero scratch that is accumulated via atomics (must be re-zeroed every call)
// ---------------------------------------------------------------------------
__global__ void zero_scratch() {
    int i = blockIdx.x * blockDim.x + threadIdx.x;
    if (i < 16 * 8 * 6400) g_A[i] = 0.f;
    if (i < 16 * 8)        g_cnt[i] = 0.f;
}

// ---------------------------------------------------------------------------
// GEMM + bias + relu:  Y[b,m,n] = relu( sum_k W[m,k] * X[b,k,n] + bias[m] )
// BM=BN=64, BK=16, 256 threads, 4x4 accum per thread.
// M % 64 == 0, K % 16 == 0, N = 6400 (% 64 == 0) -> no bounds checks.
// ---------------------------------------------------------------------------
__global__ __launch_bounds__(256) void gemm_bias_relu(
    const float* __restrict__ Wm, const float* __restrict__ bias,
    const float* __restrict__ X, float* __restrict__ Y,
    int M, int K)
{
    const int b  = blockIdx.z;
    const float* Xb = X + (size_t)b * K * NPIX;
    float*       Yb = Y + (size_t)b * M * NPIX;
    const int tm = blockIdx.y * 64;
    const int tn = blockIdx.x * 64;
    const int tid = threadIdx.x;
    const int tx = tid & 15, ty = tid >> 4;

    __shared__ float As[16][68];   // [k][m], padded
    __shared__ float Bs[16][64];   // [k][n]

    float acc[4][4];
#pragma unroll
    for (int i = 0; i < 4; i++)
#pragma unroll
        for (int j = 0; j < 4; j++) acc[i][j] = 0.f;

    const int w_row = tid >> 2;          // 0..63
    const int w_c4  = (tid & 3) * 4;     // 0,4,8,12
    const int x_row = tid >> 4;          // 0..15
    const int x_c4  = (tid & 15) * 4;    // 0..60

    for (int k0 = 0; k0 < K; k0 += 16) {
        float4 wv = *(const float4*)&Wm[(size_t)(tm + w_row) * K + k0 + w_c4];
        As[w_c4 + 0][w_row] = wv.x;
        As[w_c4 + 1][w_row] = wv.y;
        As[w_c4 + 2][w_row] = wv.z;
        As[w_c4 + 3][w_row] = wv.w;
        *(float4*)&Bs[x_row][x_c4] =
            *(const float4*)&Xb[(size_t)(k0 + x_row) * NPIX + tn + x_c4];
        __syncthreads();
#pragma unroll
        for (int kk = 0; kk < 16; kk++) {
            float4 a  = *(const float4*)&As[kk][ty * 4];
            float4 bb = *(const float4*)&Bs[kk][tx * 4];
            float av[4] = {a.x, a.y, a.z, a.w};
            float bv[4] = {bb.x, bb.y, bb.z, bb.w};
#pragma unroll
            for (int i = 0; i < 4; i++)
#pragma unroll
                for (int j = 0; j < 4; j++)
                    acc[i][j] = fmaf(av[i], bv[j], acc[i][j]);
        }
        __syncthreads();
    }

#pragma unroll
    for (int i = 0; i < 4; i++) {
        int row = tm + ty * 4 + i;
        float bvl = bias[row];
        float4 o;
        o.x = fmaxf(acc[i][0] + bvl, 0.f);
        o.y = fmaxf(acc[i][1] + bvl, 0.f);
        o.z = fmaxf(acc[i][2] + bvl, 0.f);
        o.w = fmaxf(acc[i][3] + bvl, 0.f);
        *(float4*)&Yb[(size_t)row * NPIX + tn + tx * 4] = o;
    }
}

// ---------------------------------------------------------------------------
// Build A[b,k,80,80]: for each 160x160 output pixel of class k, scatter its
// bilinear source weights back onto the 80x80 grid. Also class counts.
// jax.image.resize(bilinear, antialias=False), 80->160:
//   sample coord x = i/2 - 0.25 ; interior weights {0.25,0.75}; edges renorm to 1.
// All weights are exact dyadic rationals -> atomic order doesn't matter.
// ---------------------------------------------------------------------------
__global__ void label_kernel(const int* __restrict__ lbl) {
    int idx = blockIdx.x * blockDim.x + threadIdx.x;
    if (idx >= NB * OUTP * OUTP) return;
    int Xo = idx % OUTP;
    int t  = idx / OUTP;
    int Yo = t % OUTP;
    int b  = t / OUTP;
    int k  = lbl[idx];

    atomicAdd(&g_cnt[b * NCLS + k], 1.0f);

    int my = Yo >> 1, mx = Xo >> 1;
    int jy0, jy1, jx0, jx1;
    float wy0, wy1, wx0, wx1;
    if ((Yo & 1) == 0) {
        jy0 = my - 1; wy0 = 0.25f; jy1 = my; wy1 = 0.75f;
        if (Yo == 0) { jy0 = 0; wy0 = 0.f; wy1 = 1.f; }
    } else {
        jy0 = my; wy0 = 0.75f; jy1 = my + 1; wy1 = 0.25f;
        if (Yo == OUTP - 1) { jy1 = INP - 1; wy1 = 0.f; wy0 = 1.f; }
    }
    if ((Xo & 1) == 0) {
        jx0 = mx - 1; wx0 = 0.25f; jx1 = mx; wx1 = 0.75f;
        if (Xo == 0) { jx0 = 0; wx0 = 0.f; wx1 = 1.f; }
    } else {
        jx0 = mx; wx0 = 0.75f; jx1 = mx + 1; wx1 = 0.25f;
        if (Xo == OUTP - 1) { jx1 = INP - 1; wx1 = 0.f; wx0 = 1.f; }
    }

    float* Ab = g_A + (size_t)(b * NCLS + k) * NPIX;
    float w;
    w = wy0 * wx0; if (w != 0.f) atomicAdd(&Ab[jy0 * INP + jx0], w);
    w = wy0 * wx1; if (w != 0.f) atomicAdd(&Ab[jy0 * INP + jx1], w);
    w = wy1 * wx0; if (w != 0.f) atomicAdd(&Ab[jy1 * INP + jx0], w);
    w = wy1 * wx1; if (w != 0.f) atomicAdd(&Ab[jy1 * INP + jx1], w);
}

// ---------------------------------------------------------------------------
// pooled[b,k,c] = sum_hw A[b,k,hw] * Y3[b,c,hw] / (cnt[b,k] + 1e-8)
// grid = (c=128, b=16), 256 threads. Also writes presence (as float 0/1).
// ---------------------------------------------------------------------------
__global__ __launch_bounds__(256) void pooled_kernel(
    const float* __restrict__ Y3, float* __restrict__ out)
{
    const int c = blockIdx.x, b = blockIdx.y, tid = threadIdx.x;
    const float* y  = Y3 + ((size_t)b * 128 + c) * NPIX;
    const float* Ab = g_A + (size_t)b * NCLS * NPIX;

    float p[NCLS] = {0.f, 0.f, 0.f, 0.f, 0.f, 0.f, 0.f, 0.f};
    for (int hw = tid; hw < NPIX; hw += 256) {
        float v = y[hw];
#pragma unroll
        for (int k = 0; k < NCLS; k++)
            p[k] = fmaf(Ab[(size_t)k * NPIX + hw], v, p[k]);
    }

    __shared__ float red[NCLS][256];
#pragma unroll
    for (int k = 0; k < NCLS; k++) red[k][tid] = p[k];
    __syncthreads();
    for (int s = 128; s > 0; s >>= 1) {
        if (tid < s) {
#pragma unroll
            for (int k = 0; k < NCLS; k++) red[k][tid] += red[k][tid + s];
        }
        __syncthreads();
    }
    if (tid < NCLS) {
        float cv = g_cnt[b * NCLS + tid];
        out[(size_t)(b * NCLS + tid) * 128 + c] = red[tid][0] / (cv + 1e-8f);
        if (c == 0)
            out[16384 + b * NCLS + tid] = (cv > 0.f) ? 1.f : 0.f;
    }
}

// ---------------------------------------------------------------------------
extern "C" void kernel_launch(void* const* d_in, const int* in_sizes, int n_in,
                              void* d_out, int out_size) {
    const float* feature = (const float*)d_in[0];
    const int*   label   = (const int*)d_in[1];
    const float* w1 = (const float*)d_in[2];
    const float* b1 = (const float*)d_in[3];
    const float* w2 = (const float*)d_in[4];
    const float* b2 = (const float*)d_in[5];
    const float* w3 = (const float*)d_in[6];
    const float* b3 = (const float*)d_in[7];
    float* out = (float*)d_out;

    float *buf1, *buf2;
    cudaGetSymbolAddress((void**)&buf1, g_buf1);
    cudaGetSymbolAddress((void**)&buf2, g_buf2);

    zero_scratch<<<3200, 256>>>();

    // f1 = relu(W1 x feature + b1) : [16,512,6400]
    gemm_bias_relu<<<dim3(100, 8, 16), 256>>>(w1, b1, feature, buf1, 512, 256);
    // f  = relu(W2 x f1 + b2)      : [16,256,6400]
    gemm_bias_relu<<<dim3(100, 4, 16), 256>>>(w2, b2, buf1, buf2, 256, 512);
    // f2 = relu(W3 x f + b3)       : [16,128,6400]  (reuse buf1)
    gemm_bias_relu<<<dim3(100, 2, 16), 256>>>(w3, b3, buf2, buf1, 128, 256);

    // bilinear-backprojected onehot mass + counts
    label_kernel<<<1600, 256>>>(label);

    // masked-average pooling + presence
    pooled_kernel<<<dim3(128, 16), 256>>>(buf1, out);
}

// round 3
// speedup vs baseline: 1.8936x; 1.8936x over previous
#include <cuda_runtime.h>
#include <cuda_bf16.h>
#include <cstdint>

#define NPIX   6400
#define NBATCH 16
#define NCLS   8
#define OUTP   160
#define INP    80

// ---------------- scratch (no dynamic allocation allowed) ----------------
// ping-pong activation planes (hi/lo bf16), pixel-major [b][n][K]
__device__ __nv_bfloat16 g_XAh[(size_t)NBATCH * NPIX * 256];  // Ft, later Y2
__device__ __nv_bfloat16 g_XAl[(size_t)NBATCH * NPIX * 256];
__device__ __nv_bfloat16 g_XBh[(size_t)NBATCH * NPIX * 512];  // Y1
__device__ __nv_bfloat16 g_XBl[(size_t)NBATCH * NPIX * 512];
__device__ float g_f2[(size_t)NBATCH * NPIX * 128];           // Y3 (f32, for pooling)
// weight planes [M][K]
__device__ __nv_bfloat16 g_w1h[512 * 256], g_w1l[512 * 256];
__device__ __nv_bfloat16 g_w2h[256 * 512], g_w2l[256 * 512];
__device__ __nv_bfloat16 g_w3h[128 * 256], g_w3l[128 * 256];
__device__ float g_A[NBATCH * NCLS * NPIX];
__device__ float g_cnt[NBATCH * NCLS];
__device__ float g_part[NBATCH * 50 * NCLS * 128];

// ---------------- PTX helpers ----------------
__device__ __forceinline__ uint32_t smem_u32(const void* p) {
    uint32_t a;
    asm("{ .reg .u64 t; cvta.to.shared.u64 t, %1; cvt.u32.u64 %0, t; }" : "=r"(a) : "l"(p));
    return a;
}
__device__ __forceinline__ void cp16(uint32_t dst, const void* src) {
    asm volatile("cp.async.cg.shared.global [%0], [%1], 16;" :: "r"(dst), "l"(src));
}
__device__ __forceinline__ void cp_commit() {
    asm volatile("cp.async.commit_group;" ::: "memory");
}
__device__ __forceinline__ void ldm_x4(uint32_t* r, uint32_t addr) {
    asm volatile("ldmatrix.sync.aligned.m8n8.x4.shared.b16 {%0,%1,%2,%3}, [%4];"
                 : "=r"(r[0]), "=r"(r[1]), "=r"(r[2]), "=r"(r[3]) : "r"(addr));
}
__device__ __forceinline__ void mma_bf16(float* d, const uint32_t* a, const uint32_t* b) {
    asm volatile(
        "mma.sync.aligned.m16n8k16.row.col.f32.bf16.bf16.f32 "
        "{%0,%1,%2,%3}, {%4,%5,%6,%7}, {%8,%9}, {%0,%1,%2,%3};"
        : "+f"(d[0]), "+f"(d[1]), "+f"(d[2]), "+f"(d[3])
        : "r"(a[0]), "r"(a[1]), "r"(a[2]), "r"(a[3]), "r"(b[0]), "r"(b[1]));
}

// smem tile geometry: 128 rows x 128B; row = [hi k0..31 | lo k0..31] bf16.
// SW128 swizzle within row: byte col ^ ((row & 7) * 16)
#define TILE_BYTES 16384
#define STAGE_BYTES 32768
#define SMEM_TOTAL 65536

// ---------------------------------------------------------------------------
// bf16x3 tensor-core GEMM:
//   C[b, n(128/CTA), m(128/CTA)] = relu( X[b,n,:K] . W[m,:K]^T + bias[m] )
//   X given as hi/lo bf16 planes; W as hi/lo planes; acc = Xh.Wh + Xh.Wl + Xl.Wh.
//   mode 0: write bf16 hi/lo planes (stride M). mode 1: write f32 (stride 128).
// ---------------------------------------------------------------------------
__global__ void __launch_bounds__(256, 2)
gemm_bf16x3(const __nv_bfloat16* __restrict__ Xh, const __nv_bfloat16* __restrict__ Xl,
            const __nv_bfloat16* __restrict__ Wh, const __nv_bfloat16* __restrict__ Wl,
            const float* __restrict__ bias,
            __nv_bfloat16* __restrict__ Oh, __nv_bfloat16* __restrict__ Ol,
            float* __restrict__ Of, int M, int K, int mode)
{
    extern __shared__ char smem[];
    const uint32_t sb = smem_u32(smem);
    const int tid = threadIdx.x, wid = tid >> 5, lane = tid & 31;
    const int nw = wid & 3;          // warp n-group (4)
    const int mw = wid >> 2;         // warp m-group (2)
    const int b = blockIdx.z;
    const int n0 = blockIdx.x * 128; // pixel tile within batch
    const int mtile = blockIdx.y * 128;
    const int nch = K >> 5;

    // cp.async source base indices: thread -> (row r, plane p), 4 x 16B each
    const int cr = tid >> 1;          // 0..127
    const int cpl = tid & 1;          // 0 = hi, 1 = lo
    const uint32_t dsw = (uint32_t)((cr & 7) * 16);
    const size_t xrow = ((size_t)b * NPIX + n0 + cr) * K;    // X row elem offset
    const size_t wrow = (size_t)(mtile + cr) * K;            // W row elem offset
    const __nv_bfloat16* xsrc = cpl ? Xl : Xh;
    const __nv_bfloat16* wsrc = cpl ? Wl : Wh;

    auto load_chunk = [&](int c, int s) {
        const uint32_t abase = sb + s * STAGE_BYTES;
        const uint32_t bbase = abase + TILE_BYTES;
        const size_t koff = (size_t)c * 32;
#pragma unroll
        for (int j = 0; j < 4; j++) {
            uint32_t col = (uint32_t)(cpl * 64 + j * 16) ^ dsw;
            cp16(abase + cr * 128 + col, xsrc + xrow + koff + j * 8);
            cp16(bbase + cr * 128 + col, wsrc + wrow + koff + j * 8);
        }
        cp_commit();
    };

    float acc[2][8][4];
#pragma unroll
    for (int i = 0; i < 2; i++)
#pragma unroll
        for (int j = 0; j < 8; j++)
#pragma unroll
            for (int q = 0; q < 4; q++) acc[i][j][q] = 0.f;

    // ldmatrix address components (swizzle xor is (lane&7)*16 for every tile row)
    const int l7 = lane & 7;
    const int mi = lane >> 3;           // matrix index 0..3
    const uint32_t lsw = (uint32_t)(l7 * 16);
    // A: row = nw*32 + t*16 + (mi&1)*8 + l7 ; colq = p*4 + s*2 + (mi>>1)
    const int a_row_base = nw * 32 + (mi & 1) * 8 + l7;
    const int a_colq_base = (mi >> 1);
    // B: row = mw*64 + u*16 + (mi>>1)*8 + l7 ; colq = p*4 + s*2 + (mi&1)
    const int b_row_base = mw * 64 + (mi >> 1) * 8 + l7;
    const int b_colq_base = (mi & 1);

    load_chunk(0, 0);

    for (int c = 0; c < nch; c++) {
        if (c + 1 < nch) load_chunk(c + 1, (c + 1) & 1);
        if (c + 1 < nch)
            asm volatile("cp.async.wait_group 1;" ::: "memory");
        else
            asm volatile("cp.async.wait_group 0;" ::: "memory");
        __syncthreads();

        const uint32_t abase = sb + (c & 1) * STAGE_BYTES;
        const uint32_t bbase = abase + TILE_BYTES;

#pragma unroll
        for (int s = 0; s < 2; s++) {
            uint32_t Ah[2][4], Al[2][4];
#pragma unroll
            for (int t = 0; t < 2; t++) {
                uint32_t r0 = abase + (uint32_t)(a_row_base + t * 16) * 128;
                ldm_x4(Ah[t], r0 + (((uint32_t)(0 * 4 + s * 2 + a_colq_base) * 16) ^ lsw));
                ldm_x4(Al[t], r0 + (((uint32_t)(1 * 4 + s * 2 + a_colq_base) * 16) ^ lsw));
            }
#pragma unroll
            for (int u = 0; u < 4; u++) {
                uint32_t Bh[4], Bl[4];
                uint32_t r0 = bbase + (uint32_t)(b_row_base + u * 16) * 128;
                ldm_x4(Bh, r0 + (((uint32_t)(0 * 4 + s * 2 + b_colq_base) * 16) ^ lsw));
                ldm_x4(Bl, r0 + (((uint32_t)(1 * 4 + s * 2 + b_colq_base) * 16) ^ lsw));
#pragma unroll
                for (int nt = 0; nt < 2; nt++) {
                    mma_bf16(acc[nt][u * 2 + 0], Ah[nt], Bh + 0);
                    mma_bf16(acc[nt][u * 2 + 1], Ah[nt], Bh + 2);
                    mma_bf16(acc[nt][u * 2 + 0], Ah[nt], Bl + 0);
                    mma_bf16(acc[nt][u * 2 + 1], Ah[nt], Bl + 2);
                    mma_bf16(acc[nt][u * 2 + 0], Al[nt], Bh + 0);
                    mma_bf16(acc[nt][u * 2 + 1], Al[nt], Bh + 2);
                }
            }
        }
        __syncthreads();
    }

    // -------- epilogue --------
    const int g = lane >> 2, tg = lane & 3;
#pragma unroll
    for (int nt = 0; nt < 2; nt++) {
        const int nloc = n0 + nw * 32 + nt * 16 + g;
        const size_t bn0 = (size_t)b * NPIX + nloc;
        const size_t bn1 = bn0 + 8;
#pragma unroll
        for (int u = 0; u < 4; u++) {
#pragma unroll
            for (int h = 0; h < 2; h++) {
                const int m = mtile + mw * 64 + u * 16 + h * 8 + tg * 2;
                const float* cc = acc[nt][u * 2 + h];
                const float b0 = bias[m], b1 = bias[m + 1];
                float v00 = fmaxf(cc[0] + b0, 0.f);
                float v01 = fmaxf(cc[1] + b1, 0.f);
                float v10 = fmaxf(cc[2] + b0, 0.f);
                float v11 = fmaxf(cc[3] + b1, 0.f);
                if (mode == 0) {
                    __nv_bfloat16 h00 = __float2bfloat16(v00);
                    __nv_bfloat16 h01 = __float2bfloat16(v01);
                    __nv_bfloat16 h10 = __float2bfloat16(v10);
                    __nv_bfloat16 h11 = __float2bfloat16(v11);
                    __nv_bfloat162 hp0; hp0.x = h00; hp0.y = h01;
                    __nv_bfloat162 hp1; hp1.x = h10; hp1.y = h11;
                    __nv_bfloat162 lp0;
                    lp0.x = __float2bfloat16(v00 - __bfloat162float(h00));
                    lp0.y = __float2bfloat16(v01 - __bfloat162float(h01));
                    __nv_bfloat162 lp1;
                    lp1.x = __float2bfloat16(v10 - __bfloat162float(h10));
                    lp1.y = __float2bfloat16(v11 - __bfloat162float(h11));
                    *(__nv_bfloat162*)(Oh + bn0 * M + m) = hp0;
                    *(__nv_bfloat162*)(Ol + bn0 * M + m) = lp0;
                    *(__nv_bfloat162*)(Oh + bn1 * M + m) = hp1;
                    *(__nv_bfloat162*)(Ol + bn1 * M + m) = lp1;
                } else {
                    float2 f0 = make_float2(v00, v01);
                    float2 f1 = make_float2(v10, v11);
                    *(float2*)(Of + bn0 * 128 + m) = f0;
                    *(float2*)(Of + bn1 * 128 + m) = f1;
                }
            }
        }
    }
}

// ---------------------------------------------------------------------------
// prep: split weights into bf16 hi/lo planes; zero accumulated scratch
// ---------------------------------------------------------------------------
__global__ void prep(const float* __restrict__ w1, const float* __restrict__ w2,
                     const float* __restrict__ w3) {
    int i = blockIdx.x * 256 + threadIdx.x;
    if (i < 512 * 256) {
        float v = w1[i];
        __nv_bfloat16 h = __float2bfloat16(v);
        g_w1h[i] = h; g_w1l[i] = __float2bfloat16(v - __bfloat162float(h));
    }
    if (i < 256 * 512) {
        float v = w2[i];
        __nv_bfloat16 h = __float2bfloat16(v);
        g_w2h[i] = h; g_w2l[i] = __float2bfloat16(v - __bfloat162float(h));
    }
    if (i < 128 * 256) {
        float v = w3[i];
        __nv_bfloat16 h = __float2bfloat16(v);
        g_w3h[i] = h; g_w3l[i] = __float2bfloat16(v - __bfloat162float(h));
    }
    if (i < NBATCH * NCLS * NPIX) g_A[i] = 0.f;
    if (i < NBATCH * NCLS) g_cnt[i] = 0.f;
}

// ---------------------------------------------------------------------------
// transpose feature [b][c][n] -> hi/lo planes [b][n][256]
// ---------------------------------------------------------------------------
__global__ void transpose_feat(const float* __restrict__ f) {
    __shared__ float t[32][33];
    const int b = blockIdx.z, n0 = blockIdx.x * 32, c0 = blockIdx.y * 32;
    const int tx = threadIdx.x, ty = threadIdx.y;
    for (int i = ty; i < 32; i += 8)
        t[i][tx] = f[((size_t)b * 256 + c0 + i) * NPIX + n0 + tx];
    __syncthreads();
    for (int i = ty; i < 32; i += 8) {
        float v = t[tx][i];
        __nv_bfloat16 h = __float2bfloat16(v);
        size_t o = ((size_t)b * NPIX + n0 + i) * 256 + c0 + tx;
        g_XAh[o] = h;
        g_XAl[o] = __float2bfloat16(v - __bfloat162float(h));
    }
}

// ---------------------------------------------------------------------------
// Scatter bilinear source weights of each 160x160 labeled pixel onto 80x80 grid.
// ---------------------------------------------------------------------------
__global__ void label_kernel(const int* __restrict__ lbl) {
    __shared__ float cs[NCLS];
    const int tid = threadIdx.x;
    if (tid < NCLS) cs[tid] = 0.f;
    __syncthreads();
    const int idx = blockIdx.x * 256 + tid;
    const int Xo = idx % OUTP;
    const int t2 = idx / OUTP;
    const int Yo = t2 % OUTP;
    const int b = t2 / OUTP;
    const int k = lbl[idx];
    atomicAdd(&cs[k], 1.0f);

    const int my = Yo >> 1, mx = Xo >> 1;
    int jy0, jy1, jx0, jx1;
    float wy0, wy1, wx0, wx1;
    if ((Yo & 1) == 0) {
        jy0 = my - 1; wy0 = 0.25f; jy1 = my; wy1 = 0.75f;
        if (Yo == 0) { jy0 = 0; wy0 = 0.f; wy1 = 1.f; }
    } else {
        jy0 = my; wy0 = 0.75f; jy1 = my + 1; wy1 = 0.25f;
        if (Yo == OUTP - 1) { jy1 = INP - 1; wy1 = 0.f; wy0 = 1.f; }
    }
    if ((Xo & 1) == 0) {
        jx0 = mx - 1; wx0 = 0.25f; jx1 = mx; wx1 = 0.75f;
        if (Xo == 0) { jx0 = 0; wx0 = 0.f; wx1 = 1.f; }
    } else {
        jx0 = mx; wx0 = 0.75f; jx1 = mx + 1; wx1 = 0.25f;
        if (Xo == OUTP - 1) { jx1 = INP - 1; wx1 = 0.f; wx0 = 1.f; }
    }
    float* Ab = g_A + (size_t)(b * NCLS + k) * NPIX;
    float w;
    w = wy0 * wx0; if (w != 0.f) atomicAdd(&Ab[jy0 * INP + jx0], w);
    w = wy0 * wx1; if (w != 0.f) atomicAdd(&Ab[jy0 * INP + jx1], w);
    w = wy1 * wx0; if (w != 0.f) atomicAdd(&Ab[jy1 * INP + jx0], w);
    w = wy1 * wx1; if (w != 0.f) atomicAdd(&Ab[jy1 * INP + jx1], w);

    __syncthreads();
    if (tid < NCLS) atomicAdd(&g_cnt[b * NCLS + tid], cs[tid]);
}

// ---------------------------------------------------------------------------
// pooling: part[b,ch,k,c] = sum_{n in 128-chunk} A[b,k,n] * f2[b,n,c]
// ---------------------------------------------------------------------------
__global__ void __launch_bounds__(128) pool_stage1(const float* __restrict__ y3) {
    __shared__ float As[NCLS][128];
    const int b = blockIdx.y, ch = blockIdx.x, c = threadIdx.x;
    const int n0 = ch * 128;
#pragma unroll
    for (int k = 0; k < NCLS; k++)
        As[k][c] = g_A[(size_t)(b * NCLS + k) * NPIX + n0 + c];
    __syncthreads();
    float p[NCLS] = {0.f, 0.f, 0.f, 0.f, 0.f, 0.f, 0.f, 0.f};
    const float* yb = y3 + ((size_t)b * NPIX + n0) * 128;
    for (int i = 0; i < 128; i++) {
        const float v = yb[(size_t)i * 128 + c];
#pragma unroll
        for (int k = 0; k < NCLS; k++) p[k] = fmaf(As[k][i], v, p[k]);
    }
#pragma unroll
    for (int k = 0; k < NCLS; k++)
        g_part[(((size_t)b * 50 + ch) * NCLS + k) * 128 + c] = p[k];
}

__global__ void pool_final(float* __restrict__ out) {
    const int b = blockIdx.x;
    const int k = threadIdx.x >> 7, c = threadIdx.x & 127;
    float s = 0.f;
    for (int ch = 0; ch < 50; ch++)
        s += g_part[(((size_t)b * 50 + ch) * NCLS + k) * 128 + c];
    const float cv = g_cnt[b * NCLS + k];
    out[((size_t)b * NCLS + k) * 128 + c] = s / (cv + 1e-8f);
    if (c == 0) out[16384 + b * NCLS + k] = (cv > 0.f) ? 1.f : 0.f;
}

// ---------------------------------------------------------------------------
extern "C" void kernel_launch(void* const* d_in, const int* in_sizes, int n_in,
                              void* d_out, int out_size) {
    const float* feature = (const float*)d_in[0];
    const int*   label   = (const int*)d_in[1];
    const float* w1 = (const float*)d_in[2];
    const float* b1 = (const float*)d_in[3];
    const float* w2 = (const float*)d_in[4];
    const float* b2 = (const float*)d_in[5];
    const float* w3 = (const float*)d_in[6];
    const float* b3 = (const float*)d_in[7];
    float* out = (float*)d_out;

    void *xah, *xal, *xbh, *xbl, *f2;
    void *w1h, *w1l, *w2h, *w2l, *w3h, *w3l;
    cudaGetSymbolAddress(&xah, g_XAh); cudaGetSymbolAddress(&xal, g_XAl);
    cudaGetSymbolAddress(&xbh, g_XBh); cudaGetSymbolAddress(&xbl, g_XBl);
    cudaGetSymbolAddress(&f2, g_f2);
    cudaGetSymbolAddress(&w1h, g_w1h); cudaGetSymbolAddress(&w1l, g_w1l);
    cudaGetSymbolAddress(&w2h, g_w2h); cudaGetSymbolAddress(&w2l, g_w2l);
    cudaGetSymbolAddress(&w3h, g_w3h); cudaGetSymbolAddress(&w3l, g_w3l);

    cudaFuncSetAttribute(gemm_bf16x3, cudaFuncAttributeMaxDynamicSharedMemorySize,
                         SMEM_TOTAL);

    prep<<<3200, 256>>>(w1, w2, w3);
    transpose_feat<<<dim3(200, 8, 16), dim3(32, 8)>>>(feature);

    // Y1 = relu(W1 Ft + b1): [b][n][512] bf16 pair
    gemm_bf16x3<<<dim3(50, 4, 16), 256, SMEM_TOTAL>>>(
        (const __nv_bfloat16*)xah, (const __nv_bfloat16*)xal,
        (const __nv_bfloat16*)w1h, (const __nv_bfloat16*)w1l, b1,
        (__nv_bfloat16*)xbh, (__nv_bfloat16*)xbl, nullptr, 512, 256, 0);
    // Y2 = relu(W2 Y1 + b2): [b][n][256] bf16 pair
    gemm_bf16x3<<<dim3(50, 2, 16), 256, SMEM_TOTAL>>>(
        (const __nv_bfloat16*)xbh, (const __nv_bfloat16*)xbl,
        (const __nv_bfloat16*)w2h, (const __nv_bfloat16*)w2l, b2,
        (__nv_bfloat16*)xah, (__nv_bfloat16*)xal, nullptr, 256, 512, 0);
    // Y3 = relu(W3 Y2 + b3): [b][n][128] f32
    gemm_bf16x3<<<dim3(50, 1, 16), 256, SMEM_TOTAL>>>(
        (const __nv_bfloat16*)xah, (const __nv_bfloat16*)xal,
        (const __nv_bfloat16*)w3h, (const __nv_bfloat16*)w3l, b3,
        nullptr, nullptr, (float*)f2, 128, 256, 1);

    label_kernel<<<1600, 256>>>(label);
    pool_stage1<<<dim3(50, 16), 128>>>((const float*)f2);
    pool_final<<<16, 1024>>>(out);
}

// round 4
// speedup vs baseline: 3.7354x; 1.9727x over previous
#include <cuda_runtime.h>
#include <cuda_fp16.h>
#include <cstdint>

#define NPIX   6400
#define NBATCH 16
#define NCLS   8
#define OUTP   160
#define INP    80

// ---------------- scratch (no dynamic allocation allowed) ----------------
__device__ __half g_XA[(size_t)NBATCH * NPIX * 256];  // Ft, later Y2  [b][n][K]
__device__ __half g_XB[(size_t)NBATCH * NPIX * 512];  // Y1
__device__ float  g_f2[(size_t)NBATCH * NPIX * 128];  // Y3 (f32, for pooling)
__device__ __half g_w1[512 * 256];
__device__ __half g_w2[256 * 512];
__device__ __half g_w3[128 * 256];
__device__ float g_A[NBATCH * NCLS * NPIX];
__device__ float g_cnt[NBATCH * NCLS];
__device__ float g_part[NBATCH * 50 * NCLS * 128];

// ---------------- PTX helpers ----------------
__device__ __forceinline__ uint32_t smem_u32(const void* p) {
    uint32_t a;
    asm("{ .reg .u64 t; cvta.to.shared.u64 t, %1; cvt.u32.u64 %0, t; }" : "=r"(a) : "l"(p));
    return a;
}
__device__ __forceinline__ void cp16(uint32_t dst, const void* src) {
    asm volatile("cp.async.cg.shared.global [%0], [%1], 16;" :: "r"(dst), "l"(src));
}
__device__ __forceinline__ void ldm_x4(uint32_t* r, uint32_t addr) {
    asm volatile("ldmatrix.sync.aligned.m8n8.x4.shared.b16 {%0,%1,%2,%3}, [%4];"
                 : "=r"(r[0]), "=r"(r[1]), "=r"(r[2]), "=r"(r[3]) : "r"(addr));
}
__device__ __forceinline__ void mma_f16(float* d, const uint32_t* a, const uint32_t* b) {
    asm volatile(
        "mma.sync.aligned.m16n8k16.row.col.f32.f16.f16.f32 "
        "{%0,%1,%2,%3}, {%4,%5,%6,%7}, {%8,%9}, {%0,%1,%2,%3};"
        : "+f"(d[0]), "+f"(d[1]), "+f"(d[2]), "+f"(d[3])
        : "r"(a[0]), "r"(a[1]), "r"(a[2]), "r"(a[3]), "r"(b[0]), "r"(b[1]));
}

// smem tile: 128 rows x 128B (64 fp16 = one K-chunk). swizzle: col16 ^= (row&7)
#define TILE_BYTES  16384
#define STAGE_BYTES 32768
#define SMEM_TOTAL  65536

// ---------------------------------------------------------------------------
// fp16 tensor-core GEMM: C[b, n(128/CTA), m(128/CTA)] = relu(X[n,:K].W[m,:K]^T + bias)
//   mode 0: write fp16 (stride M). mode 1: write f32 (stride 128).
// ---------------------------------------------------------------------------
__global__ void __launch_bounds__(256, 2)
gemm_f16(const __half* __restrict__ X, const __half* __restrict__ W,
         const float* __restrict__ bias,
         __half* __restrict__ Oh, float* __restrict__ Of, int M, int K, int mode)
{
    extern __shared__ char smem[];
    const uint32_t sb = smem_u32(smem);
    const int tid = threadIdx.x, wid = tid >> 5, lane = tid & 31;
    const int nw = wid & 3;          // warp n-group (4)
    const int mw = wid >> 2;         // warp m-group (2)
    const int b = blockIdx.z;
    const int n0 = blockIdx.x * 128;
    const int mtile = blockIdx.y * 128;
    const int nch = K >> 6;          // K-chunks of 64

    // cp.async: thread -> one 128B row (8 x 16B). tid<128: A rows, else B rows.
    const int cr = tid & 127;
    const int isB = tid >> 7;
    const uint32_t rsw = (uint32_t)((cr & 7) * 16);
    const __half* src = isB ? (W + (size_t)(mtile + cr) * K)
                            : (X + ((size_t)b * NPIX + n0 + cr) * K);
    const uint32_t dbase = sb + (uint32_t)isB * TILE_BYTES + (uint32_t)cr * 128;

    auto load_chunk = [&](int c, int s) {
        const uint32_t d0 = dbase + (uint32_t)s * STAGE_BYTES;
        const __half* s0 = src + (size_t)c * 64;
#pragma unroll
        for (int j = 0; j < 8; j++)
            cp16(d0 + (((uint32_t)j * 16) ^ rsw), s0 + j * 8);
        asm volatile("cp.async.commit_group;" ::: "memory");
    };

    float acc[2][8][4];
#pragma unroll
    for (int i = 0; i < 2; i++)
#pragma unroll
        for (int j = 0; j < 8; j++)
#pragma unroll
            for (int q = 0; q < 4; q++) acc[i][j][q] = 0.f;

    const int l7 = lane & 7;
    const int mi = lane >> 3;
    const uint32_t lsw = (uint32_t)(l7 * 16);
    const int a_row_base = nw * 32 + (mi & 1) * 8 + l7;
    const int a_colq = (mi >> 1);
    const int b_row_base = mw * 64 + (mi >> 1) * 8 + l7;
    const int b_colq = (mi & 1);

    load_chunk(0, 0);

    for (int c = 0; c < nch; c++) {
        if (c + 1 < nch) {
            load_chunk(c + 1, (c + 1) & 1);
            asm volatile("cp.async.wait_group 1;" ::: "memory");
        } else {
            asm volatile("cp.async.wait_group 0;" ::: "memory");
        }
        __syncthreads();

        const uint32_t abase = sb + (uint32_t)(c & 1) * STAGE_BYTES;
        const uint32_t bbase = abase + TILE_BYTES;

#pragma unroll
        for (int s = 0; s < 4; s++) {
            uint32_t Af[2][4];
#pragma unroll
            for (int t = 0; t < 2; t++)
                ldm_x4(Af[t], abase + (uint32_t)(a_row_base + t * 16) * 128
                              + (((uint32_t)(s * 2 + a_colq) * 16) ^ lsw));
#pragma unroll
            for (int u = 0; u < 4; u++) {
                uint32_t Bf[4];
                ldm_x4(Bf, bbase + (uint32_t)(b_row_base + u * 16) * 128
                           + (((uint32_t)(s * 2 + b_colq) * 16) ^ lsw));
#pragma unroll
                for (int nt = 0; nt < 2; nt++) {
                    mma_f16(acc[nt][u * 2 + 0], Af[nt], Bf + 0);
                    mma_f16(acc[nt][u * 2 + 1], Af[nt], Bf + 2);
                }
            }
        }
        __syncthreads();
    }

    // -------- epilogue --------
    const int g = lane >> 2, tg = lane & 3;
#pragma unroll
    for (int nt = 0; nt < 2; nt++) {
        const int nloc = n0 + nw * 32 + nt * 16 + g;
        const size_t bn0 = (size_t)b * NPIX + nloc;
        const size_t bn1 = bn0 + 8;
#pragma unroll
        for (int u = 0; u < 4; u++) {
#pragma unroll
            for (int h = 0; h < 2; h++) {
                const int m = mtile + mw * 64 + u * 16 + h * 8 + tg * 2;
                const float* cc = acc[nt][u * 2 + h];
                const float b0 = bias[m], b1 = bias[m + 1];
                float v00 = fmaxf(cc[0] + b0, 0.f);
                float v01 = fmaxf(cc[1] + b1, 0.f);
                float v10 = fmaxf(cc[2] + b0, 0.f);
                float v11 = fmaxf(cc[3] + b1, 0.f);
                if (mode == 0) {
                    __half2 p0; p0.x = __float2half_rn(v00); p0.y = __float2half_rn(v01);
                    __half2 p1; p1.x = __float2half_rn(v10); p1.y = __float2half_rn(v11);
                    *(__half2*)(Oh + bn0 * M + m) = p0;
                    *(__half2*)(Oh + bn1 * M + m) = p1;
                } else {
                    *(float2*)(Of + bn0 * 128 + m) = make_float2(v00, v01);
                    *(float2*)(Of + bn1 * 128 + m) = make_float2(v10, v11);
                }
            }
        }
    }
}

// ---------------------------------------------------------------------------
__global__ void prep(const float* __restrict__ w1, const float* __restrict__ w2,
                     const float* __restrict__ w3) {
    int i = blockIdx.x * 256 + threadIdx.x;
    if (i < 512 * 256) g_w1[i] = __float2half_rn(w1[i]);
    if (i < 256 * 512) g_w2[i] = __float2half_rn(w2[i]);
    if (i < 128 * 256) g_w3[i] = __float2half_rn(w3[i]);
    if (i < NBATCH * NCLS * NPIX) g_A[i] = 0.f;
    if (i < NBATCH * NCLS) g_cnt[i] = 0.f;
}

// transpose feature [b][c][n] -> fp16 [b][n][256]
__global__ void transpose_feat(const float* __restrict__ f) {
    __shared__ float t[32][33];
    const int b = blockIdx.z, n0 = blockIdx.x * 32, c0 = blockIdx.y * 32;
    const int tx = threadIdx.x, ty = threadIdx.y;
    for (int i = ty; i < 32; i += 8)
        t[i][tx] = f[((size_t)b * 256 + c0 + i) * NPIX + n0 + tx];
    __syncthreads();
    for (int i = ty; i < 32; i += 8)
        g_XA[((size_t)b * NPIX + n0 + i) * 256 + c0 + tx] = __float2half_rn(t[tx][i]);
}

// ---------------------------------------------------------------------------
__global__ void label_kernel(const int* __restrict__ lbl) {
    __shared__ float cs[NCLS];
    const int tid = threadIdx.x;
    if (tid < NCLS) cs[tid] = 0.f;
    __syncthreads();
    const int idx = blockIdx.x * 256 + tid;
    const int Xo = idx % OUTP;
    const int t2 = idx / OUTP;
    const int Yo = t2 % OUTP;
    const int b = t2 / OUTP;
    const int k = lbl[idx];
    atomicAdd(&cs[k], 1.0f);

    const int my = Yo >> 1, mx = Xo >> 1;
    int jy0, jy1, jx0, jx1;
    float wy0, wy1, wx0, wx1;
    if ((Yo & 1) == 0) {
        jy0 = my - 1; wy0 = 0.25f; jy1 = my; wy1 = 0.75f;
        if (Yo == 0) { jy0 = 0; wy0 = 0.f; wy1 = 1.f; }
    } else {
        jy0 = my; wy0 = 0.75f; jy1 = my + 1; wy1 = 0.25f;
        if (Yo == OUTP - 1) { jy1 = INP - 1; wy1 = 0.f; wy0 = 1.f; }
    }
    if ((Xo & 1) == 0) {
        jx0 = mx - 1; wx0 = 0.25f; jx1 = mx; wx1 = 0.75f;
        if (Xo == 0) { jx0 = 0; wx0 = 0.f; wx1 = 1.f; }
    } else {
        jx0 = mx; wx0 = 0.75f; jx1 = mx + 1; wx1 = 0.25f;
        if (Xo == OUTP - 1) { jx1 = INP - 1; wx1 = 0.f; wx0 = 1.f; }
    }
    float* Ab = g_A + (size_t)(b * NCLS + k) * NPIX;
    float w;
    w = wy0 * wx0; if (w != 0.f) atomicAdd(&Ab[jy0 * INP + jx0], w);
    w = wy0 * wx1; if (w != 0.f) atomicAdd(&Ab[jy0 * INP + jx1], w);
    w = wy1 * wx0; if (w != 0.f) atomicAdd(&Ab[jy1 * INP + jx0], w);
    w = wy1 * wx1; if (w != 0.f) atomicAdd(&Ab[jy1 * INP + jx1], w);

    __syncthreads();
    if (tid < NCLS) atomicAdd(&g_cnt[b * NCLS + tid], cs[tid]);
}

// ---------------------------------------------------------------------------
__global__ void __launch_bounds__(128) pool_stage1(const float* __restrict__ y3) {
    __shared__ float As[NCLS][128];
    const int b = blockIdx.y, ch = blockIdx.x, c = threadIdx.x;
    const int n0 = ch * 128;
#pragma unroll
    for (int k = 0; k < NCLS; k++)
        As[k][c] = g_A[(size_t)(b * NCLS + k) * NPIX + n0 + c];
    __syncthreads();
    float p[NCLS] = {0.f, 0.f, 0.f, 0.f, 0.f, 0.f, 0.f, 0.f};
    const float* yb = y3 + ((size_t)b * NPIX + n0) * 128;
    for (int i = 0; i < 128; i++) {
        const float v = yb[(size_t)i * 128 + c];
#pragma unroll
        for (int k = 0; k < NCLS; k++) p[k] = fmaf(As[k][i], v, p[k]);
    }
#pragma unroll
    for (int k = 0; k < NCLS; k++)
        g_part[(((size_t)b * 50 + ch) * NCLS + k) * 128 + c] = p[k];
}

__global__ void pool_final(float* __restrict__ out) {
    const int b = blockIdx.x;
    const int k = threadIdx.x >> 7, c = threadIdx.x & 127;
    float s = 0.f;
    for (int ch = 0; ch < 50; ch++)
        s += g_part[(((size_t)b * 50 + ch) * NCLS + k) * 128 + c];
    const float cv = g_cnt[b * NCLS + k];
    out[((size_t)b * NCLS + k) * 128 + c] = s / (cv + 1e-8f);
    if (c == 0) out[16384 + b * NCLS + k] = (cv > 0.f) ? 1.f : 0.f;
}

// ---------------------------------------------------------------------------
extern "C" void kernel_launch(void* const* d_in, const int* in_sizes, int n_in,
                              void* d_out, int out_size) {
    const float* feature = (const float*)d_in[0];
    const int*   label   = (const int*)d_in[1];
    const float* w1 = (const float*)d_in[2];
    const float* b1 = (const float*)d_in[3];
    const float* w2 = (const float*)d_in[4];
    const float* b2 = (const float*)d_in[5];
    const float* w3 = (const float*)d_in[6];
    const float* b3 = (const float*)d_in[7];
    float* out = (float*)d_out;

    void *xa, *xb, *f2, *w1d, *w2d, *w3d;
    cudaGetSymbolAddress(&xa, g_XA);
    cudaGetSymbolAddress(&xb, g_XB);
    cudaGetSymbolAddress(&f2, g_f2);
    cudaGetSymbolAddress(&w1d, g_w1);
    cudaGetSymbolAddress(&w2d, g_w2);
    cudaGetSymbolAddress(&w3d, g_w3);

    cudaFuncSetAttribute(gemm_f16, cudaFuncAttributeMaxDynamicSharedMemorySize,
                         SMEM_TOTAL);

    prep<<<3200, 256>>>(w1, w2, w3);
    transpose_feat<<<dim3(200, 8, 16), dim3(32, 8)>>>(feature);

    // Y1 = relu(W1 Ft + b1): [b][n][512] fp16
    gemm_f16<<<dim3(50, 4, 16), 256, SMEM_TOTAL>>>(
        (const __half*)xa, (const __half*)w1d, b1,
        (__half*)xb, nullptr, 512, 256, 0);
    // Y2 = relu(W2 Y1 + b2): [b][n][256] fp16
    gemm_f16<<<dim3(50, 2, 16), 256, SMEM_TOTAL>>>(
        (const __half*)xb, (const __half*)w2d, b2,
        (__half*)xa, nullptr, 256, 512, 0);
    // Y3 = relu(W3 Y2 + b3): [b][n][128] f32
    gemm_f16<<<dim3(50, 1, 16), 256, SMEM_TOTAL>>>(
        (const __half*)xa, (const __half*)w3d, b3,
        nullptr, (float*)f2, 128, 256, 1);

    label_kernel<<<1600, 256>>>(label);
    pool_stage1<<<dim3(50, 16), 128>>>((const float*)f2);
    pool_final<<<16, 1024>>>(out);
}

// round 5
// speedup vs baseline: 4.0523x; 1.0848x over previous
#include <cuda_runtime.h>
#include <cuda_fp16.h>
#include <cstdint>

#define NPIX   6400
#define NBATCH 16
#define NCLS   8
#define OUTP   160
#define INP    80

// ---------------- scratch (no dynamic allocation allowed) ----------------
__device__ __half g_XA[(size_t)NBATCH * NPIX * 256];  // Ft, later Y2  [b][n][K]
__device__ __half g_XB[(size_t)NBATCH * NPIX * 512];  // Y1
__device__ float  g_f2[(size_t)NBATCH * NPIX * 128];  // Y3 (f32, for pooling)
__device__ __half g_w1[512 * 256];
__device__ __half g_w2[256 * 512];
__device__ __half g_w3[128 * 256];
__device__ float g_A[NBATCH * NCLS * NPIX];
__device__ float g_cnt[NBATCH * NCLS];
__device__ float g_part[NBATCH * 50 * NCLS * 128];

// ---------------- PTX helpers ----------------
__device__ __forceinline__ uint32_t smem_u32(const void* p) {
    uint32_t a;
    asm("{ .reg .u64 t; cvta.to.shared.u64 t, %1; cvt.u32.u64 %0, t; }" : "=r"(a) : "l"(p));
    return a;
}
__device__ __forceinline__ void cp16(uint32_t dst, const void* src) {
    asm volatile("cp.async.cg.shared.global [%0], [%1], 16;" :: "r"(dst), "l"(src));
}
__device__ __forceinline__ void cp_commit() {
    asm volatile("cp.async.commit_group;" ::: "memory");
}
__device__ __forceinline__ void ldm_x4(uint32_t* r, uint32_t addr) {
    asm volatile("ldmatrix.sync.aligned.m8n8.x4.shared.b16 {%0,%1,%2,%3}, [%4];"
                 : "=r"(r[0]), "=r"(r[1]), "=r"(r[2]), "=r"(r[3]) : "r"(addr));
}
__device__ __forceinline__ void mma_f16(float* d, const uint32_t* a, const uint32_t* b) {
    asm volatile(
        "mma.sync.aligned.m16n8k16.row.col.f32.f16.f16.f32 "
        "{%0,%1,%2,%3}, {%4,%5,%6,%7}, {%8,%9}, {%0,%1,%2,%3};"
        : "+f"(d[0]), "+f"(d[1]), "+f"(d[2]), "+f"(d[3])
        : "r"(a[0]), "r"(a[1]), "r"(a[2]), "r"(a[3]), "r"(b[0]), "r"(b[1]));
}

// smem tile: 128 rows x 128B (64 fp16 = one K-chunk). swizzle: col16 ^= (row&7)
#define TILE_BYTES  16384
#define STAGE_BYTES 32768
#define NSTAGE      3
#define SMEM_TOTAL  (NSTAGE * STAGE_BYTES)   // 98304

// ---------------------------------------------------------------------------
// fp16 tensor-core GEMM (3-stage cp.async multistage, 1 sync / K-chunk):
//   C[b, n(128/CTA), m(128/CTA)] = relu(X[n,:K].W[m,:K]^T + bias)
//   MODE 0: write fp16 (stride M). MODE 1: write f32 (stride 128).
// ---------------------------------------------------------------------------
template <int K, int MODE>
__global__ void __launch_bounds__(256, 2)
gemm_f16(const __half* __restrict__ X, const __half* __restrict__ W,
         const float* __restrict__ bias,
         __half* __restrict__ Oh, float* __restrict__ Of, int M)
{
    extern __shared__ char smem[];
    const uint32_t sb = smem_u32(smem);
    const int tid = threadIdx.x, wid = tid >> 5, lane = tid & 31;
    const int nw = wid & 3;          // warp n-group (4)
    const int mw = wid >> 2;         // warp m-group (2)
    const int b = blockIdx.z;
    const int n0 = blockIdx.x * 128;
    const int mtile = blockIdx.y * 128;
    constexpr int NCH = K >> 6;      // K-chunks of 64

    // cp.async: thread -> one 128B row (8 x 16B). tid<128: A rows, else B rows.
    const int cr = tid & 127;
    const int isB = tid >> 7;
    const uint32_t rsw = (uint32_t)((cr & 7) * 16);
    const __half* src = isB ? (W + (size_t)(mtile + cr) * K)
                            : (X + ((size_t)b * NPIX + n0 + cr) * K);
    const uint32_t dbase = sb + (uint32_t)isB * TILE_BYTES + (uint32_t)cr * 128;

    auto load_chunk = [&](int c, int s) {
        const uint32_t d0 = dbase + (uint32_t)s * STAGE_BYTES;
        const __half* s0 = src + (size_t)c * 64;
#pragma unroll
        for (int j = 0; j < 8; j++)
            cp16(d0 + (((uint32_t)j * 16) ^ rsw), s0 + j * 8);
        cp_commit();
    };

    float acc[2][8][4];
#pragma unroll
    for (int i = 0; i < 2; i++)
#pragma unroll
        for (int j = 0; j < 8; j++)
#pragma unroll
            for (int q = 0; q < 4; q++) acc[i][j][q] = 0.f;

    const int l7 = lane & 7;
    const int mi = lane >> 3;
    const uint32_t lsw = (uint32_t)(l7 * 16);
    const int a_row_base = nw * 32 + (mi & 1) * 8 + l7;
    const int a_colq = (mi >> 1);
    const int b_row_base = mw * 64 + (mi >> 1) * 8 + l7;
    const int b_colq = (mi & 1);

    // prologue: stages 0,1
    load_chunk(0, 0);
    load_chunk(1, 1);

#pragma unroll
    for (int c = 0; c < NCH; c++) {
        // chunk c resident once <=1 newer group pending
        asm volatile("cp.async.wait_group 1;" ::: "memory");
        __syncthreads();

        // issue load for chunk c+2 into stage (c+2)%3 (consumed at iter c-1; sync above
        // guarantees all warps finished it). Always commit to keep group count uniform.
        if (c + 2 < NCH) load_chunk(c + 2, (c + 2) % NSTAGE);
        else             cp_commit();

        const uint32_t abase = sb + (uint32_t)(c % NSTAGE) * STAGE_BYTES;
        const uint32_t bbase = abase + TILE_BYTES;

#pragma unroll
        for (int s = 0; s < 4; s++) {
            uint32_t Af[2][4];
#pragma unroll
            for (int t = 0; t < 2; t++)
                ldm_x4(Af[t], abase + (uint32_t)(a_row_base + t * 16) * 128
                              + (((uint32_t)(s * 2 + a_colq) * 16) ^ lsw));
#pragma unroll
            for (int u = 0; u < 4; u++) {
                uint32_t Bf[4];
                ldm_x4(Bf, bbase + (uint32_t)(b_row_base + u * 16) * 128
                           + (((uint32_t)(s * 2 + b_colq) * 16) ^ lsw));
#pragma unroll
                for (int nt = 0; nt < 2; nt++) {
                    mma_f16(acc[nt][u * 2 + 0], Af[nt], Bf + 0);
                    mma_f16(acc[nt][u * 2 + 1], Af[nt], Bf + 2);
                }
            }
        }
    }

    // -------- epilogue --------
    const int g = lane >> 2, tg = lane & 3;
#pragma unroll
    for (int nt = 0; nt < 2; nt++) {
        const int nloc = n0 + nw * 32 + nt * 16 + g;
        const size_t bn0 = (size_t)b * NPIX + nloc;
        const size_t bn1 = bn0 + 8;
#pragma unroll
        for (int u = 0; u < 4; u++) {
#pragma unroll
            for (int h = 0; h < 2; h++) {
                const int m = mtile + mw * 64 + u * 16 + h * 8 + tg * 2;
                const float* cc = acc[nt][u * 2 + h];
                const float b0 = bias[m], b1 = bias[m + 1];
                float v00 = fmaxf(cc[0] + b0, 0.f);
                float v01 = fmaxf(cc[1] + b1, 0.f);
                float v10 = fmaxf(cc[2] + b0, 0.f);
                float v11 = fmaxf(cc[3] + b1, 0.f);
                if (MODE == 0) {
                    __half2 p0; p0.x = __float2half_rn(v00); p0.y = __float2half_rn(v01);
                    __half2 p1; p1.x = __float2half_rn(v10); p1.y = __float2half_rn(v11);
                    *(__half2*)(Oh + bn0 * M + m) = p0;
                    *(__half2*)(Oh + bn1 * M + m) = p1;
                } else {
                    *(float2*)(Of + bn0 * 128 + m) = make_float2(v00, v01);
                    *(float2*)(Of + bn1 * 128 + m) = make_float2(v10, v11);
                }
            }
        }
    }
}

// ---------------------------------------------------------------------------
__global__ void prep(const float* __restrict__ w1, const float* __restrict__ w2,
                     const float* __restrict__ w3) {
    int i = blockIdx.x * 256 + threadIdx.x;
    if (i < 512 * 256) g_w1[i] = __float2half_rn(w1[i]);
    if (i < 256 * 512) g_w2[i] = __float2half_rn(w2[i]);
    if (i < 128 * 256) g_w3[i] = __float2half_rn(w3[i]);
    if (i < NBATCH * NCLS * NPIX) g_A[i] = 0.f;
    if (i < NBATCH * NCLS) g_cnt[i] = 0.f;
}

// transpose feature [b][c][n] -> fp16 [b][n][256]
__global__ void transpose_feat(const float* __restrict__ f) {
    __shared__ float t[32][33];
    const int b = blockIdx.z, n0 = blockIdx.x * 32, c0 = blockIdx.y * 32;
    const int tx = threadIdx.x, ty = threadIdx.y;
    for (int i = ty; i < 32; i += 8)
        t[i][tx] = f[((size_t)b * 256 + c0 + i) * NPIX + n0 + tx];
    __syncthreads();
    for (int i = ty; i < 32; i += 8)
        g_XA[((size_t)b * NPIX + n0 + i) * 256 + c0 + tx] = __float2half_rn(t[tx][i]);
}

// ---------------------------------------------------------------------------
__global__ void label_kernel(const int* __restrict__ lbl) {
    __shared__ float cs[NCLS];
    const int tid = threadIdx.x;
    if (tid < NCLS) cs[tid] = 0.f;
    __syncthreads();
    const int idx = blockIdx.x * 256 + tid;
    const int Xo = idx % OUTP;
    const int t2 = idx / OUTP;
    const int Yo = t2 % OUTP;
    const int b = t2 / OUTP;
    const int k = lbl[idx];
    atomicAdd(&cs[k], 1.0f);

    const int my = Yo >> 1, mx = Xo >> 1;
    int jy0, jy1, jx0, jx1;
    float wy0, wy1, wx0, wx1;
    if ((Yo & 1) == 0) {
        jy0 = my - 1; wy0 = 0.25f; jy1 = my; wy1 = 0.75f;
        if (Yo == 0) { jy0 = 0; wy0 = 0.f; wy1 = 1.f; }
    } else {
        jy0 = my; wy0 = 0.75f; jy1 = my + 1; wy1 = 0.25f;
        if (Yo == OUTP - 1) { jy1 = INP - 1; wy1 = 0.f; wy0 = 1.f; }
    }
    if ((Xo & 1) == 0) {
        jx0 = mx - 1; wx0 = 0.25f; jx1 = mx; wx1 = 0.75f;
        if (Xo == 0) { jx0 = 0; wx0 = 0.f; wx1 = 1.f; }
    } else {
        jx0 = mx; wx0 = 0.75f; jx1 = mx + 1; wx1 = 0.25f;
        if (Xo == OUTP - 1) { jx1 = INP - 1; wx1 = 0.f; wx0 = 1.f; }
    }
    float* Ab = g_A + (size_t)(b * NCLS + k) * NPIX;
    float w;
    w = wy0 * wx0; if (w != 0.f) atomicAdd(&Ab[jy0 * INP + jx0], w);
    w = wy0 * wx1; if (w != 0.f) atomicAdd(&Ab[jy0 * INP + jx1], w);
    w = wy1 * wx0; if (w != 0.f) atomicAdd(&Ab[jy1 * INP + jx0], w);
    w = wy1 * wx1; if (w != 0.f) atomicAdd(&Ab[jy1 * INP + jx1], w);

    __syncthreads();
    if (tid < NCLS) atomicAdd(&g_cnt[b * NCLS + tid], cs[tid]);
}

// ---------------------------------------------------------------------------
__global__ void __launch_bounds__(128) pool_stage1(const float* __restrict__ y3) {
    __shared__ float As[NCLS][128];
    const int b = blockIdx.y, ch = blockIdx.x, c = threadIdx.x;
    const int n0 = ch * 128;
#pragma unroll
    for (int k = 0; k < NCLS; k++)
        As[k][c] = g_A[(size_t)(b * NCLS + k) * NPIX + n0 + c];
    __syncthreads();
    float p[NCLS] = {0.f, 0.f, 0.f, 0.f, 0.f, 0.f, 0.f, 0.f};
    const float* yb = y3 + ((size_t)b * NPIX + n0) * 128;
    for (int i = 0; i < 128; i++) {
        const float v = yb[(size_t)i * 128 + c];
#pragma unroll
        for (int k = 0; k < NCLS; k++) p[k] = fmaf(As[k][i], v, p[k]);
    }
#pragma unroll
    for (int k = 0; k < NCLS; k++)
        g_part[(((size_t)b * 50 + ch) * NCLS + k) * 128 + c] = p[k];
}

__global__ void pool_final(float* __restrict__ out) {
    const int b = blockIdx.x;
    const int k = threadIdx.x >> 7, c = threadIdx.x & 127;
    float s = 0.f;
    for (int ch = 0; ch < 50; ch++)
        s += g_part[(((size_t)b * 50 + ch) * NCLS + k) * 128 + c];
    const float cv = g_cnt[b * NCLS + k];
    out[((size_t)b * NCLS + k) * 128 + c] = s / (cv + 1e-8f);
    if (c == 0) out[16384 + b * NCLS + k] = (cv > 0.f) ? 1.f : 0.f;
}

// ---------------------------------------------------------------------------
extern "C" void kernel_launch(void* const* d_in, const int* in_sizes, int n_in,
                              void* d_out, int out_size) {
    const float* feature = (const float*)d_in[0];
    const int*   label   = (const int*)d_in[1];
    const float* w1 = (const float*)d_in[2];
    const float* b1 = (const float*)d_in[3];
    const float* w2 = (const float*)d_in[4];
    const float* b2 = (const float*)d_in[5];
    const float* w3 = (const float*)d_in[6];
    const float* b3 = (const float*)d_in[7];
    float* out = (float*)d_out;

    void *xa, *xb, *f2, *w1d, *w2d, *w3d;
    cudaGetSymbolAddress(&xa, g_XA);
    cudaGetSymbolAddress(&xb, g_XB);
    cudaGetSymbolAddress(&f2, g_f2);
    cudaGetSymbolAddress(&w1d, g_w1);
    cudaGetSymbolAddress(&w2d, g_w2);
    cudaGetSymbolAddress(&w3d, g_w3);

    cudaFuncSetAttribute(gemm_f16<256, 0>, cudaFuncAttributeMaxDynamicSharedMemorySize, SMEM_TOTAL);
    cudaFuncSetAttribute(gemm_f16<512, 0>, cudaFuncAttributeMaxDynamicSharedMemorySize, SMEM_TOTAL);
    cudaFuncSetAttribute(gemm_f16<256, 1>, cudaFuncAttributeMaxDynamicSharedMemorySize, SMEM_TOTAL);

    prep<<<3200, 256>>>(w1, w2, w3);
    transpose_feat<<<dim3(200, 8, 16), dim3(32, 8)>>>(feature);

    // Y1 = relu(W1 Ft + b1): [b][n][512] fp16
    gemm_f16<256, 0><<<dim3(50, 4, 16), 256, SMEM_TOTAL>>>(
        (const __half*)xa, (const __half*)w1d, b1, (__half*)xb, nullptr, 512);
    // Y2 = relu(W2 Y1 + b2): [b][n][256] fp16
    gemm_f16<512, 0><<<dim3(50, 2, 16), 256, SMEM_TOTAL>>>(
        (const __half*)xb, (const __half*)w2d, b2, (__half*)xa, nullptr, 256);
    // Y3 = relu(W3 Y2 + b3): [b][n][128] f32
    gemm_f16<256, 1><<<dim3(50, 1, 16), 256, SMEM_TOTAL>>>(
        (const __half*)xa, (const __half*)w3d, b3, nullptr, (float*)f2, 128);

    label_kernel<<<1600, 256>>>(label);
    pool_stage1<<<dim3(50, 16), 128>>>((const float*)f2);
    pool_final<<<16, 1024>>>(out);
}

// round 6
// speedup vs baseline: 5.7523x; 1.4195x over previous
#include <cuda_runtime.h>
#include <cuda_fp16.h>
#include <cstdint>

#define NPIX   6400
#define NBATCH 16
#define NCLS   8
#define OUTP   160
#define INP    80

// ---------------- scratch (no dynamic allocation allowed) ----------------
__device__ __half g_XA[(size_t)NBATCH * NPIX * 256];  // Ft, later Y2  [b][n][K]
__device__ __half g_XB[(size_t)NBATCH * NPIX * 512];  // Y1
__device__ __half g_w1[512 * 256];
__device__ __half g_w2[256 * 512];
__device__ __half g_w3[128 * 256];
__device__ float g_A[NBATCH * NCLS * NPIX];
__device__ float g_cnt[NBATCH * NCLS];
__device__ float g_part[NBATCH * 25 * NCLS * 128];

// ---------------- PTX helpers ----------------
__device__ __forceinline__ uint32_t smem_u32(const void* p) {
    uint32_t a;
    asm("{ .reg .u64 t; cvta.to.shared.u64 t, %1; cvt.u32.u64 %0, t; }" : "=r"(a) : "l"(p));
    return a;
}
__device__ __forceinline__ void cp16(uint32_t dst, const void* src) {
    asm volatile("cp.async.cg.shared.global [%0], [%1], 16;" :: "r"(dst), "l"(src));
}
__device__ __forceinline__ void cp_commit() {
    asm volatile("cp.async.commit_group;" ::: "memory");
}
__device__ __forceinline__ void ldm_x4(uint32_t* r, uint32_t addr) {
    asm volatile("ldmatrix.sync.aligned.m8n8.x4.shared.b16 {%0,%1,%2,%3}, [%4];"
                 : "=r"(r[0]), "=r"(r[1]), "=r"(r[2]), "=r"(r[3]) : "r"(addr));
}
__device__ __forceinline__ void mma_f16(float* d, const uint32_t* a, const uint32_t* b) {
    asm volatile(
        "mma.sync.aligned.m16n8k16.row.col.f32.f16.f16.f32 "
        "{%0,%1,%2,%3}, {%4,%5,%6,%7}, {%8,%9}, {%0,%1,%2,%3};"
        : "+f"(d[0]), "+f"(d[1]), "+f"(d[2]), "+f"(d[3])
        : "r"(a[0]), "r"(a[1]), "r"(a[2]), "r"(a[3]), "r"(b[0]), "r"(b[1]));
}

// smem: stage = A tile (256 rows x 128B) + B tile (128 rows x 128B) = 48KB, 3 stages
#define A_TILE_BYTES 32768
#define STAGE_BYTES  49152
#define NSTAGE       3
#define SMEM_TOTAL   (NSTAGE * STAGE_BYTES)   // 147456
// MODE 1 epilogue overlay: Ysm 256x128 f32 (131072 B) then As 8x256 f32 (8192 B)
#define YSM_OFF      0
#define AS_OFF       131072

// ---------------------------------------------------------------------------
// fp16 tensor-core GEMM, CTA tile 256n x 128m, 8 warps of 64n x 64m.
//   C[b, n, m] = relu(X[n,:K].W[m,:K]^T + bias[m])
//   MODE 0: write fp16 (stride M).
//   MODE 1: fused masked-pooling: partials p[k,c] += A[b,k,n]*C[n,c] -> Pf.
// ---------------------------------------------------------------------------
template <int K, int MODE>
__global__ void __launch_bounds__(256, 1)
gemm_f16(const __half* __restrict__ X, const __half* __restrict__ W,
         const float* __restrict__ bias,
         __half* __restrict__ Oh, float* __restrict__ Pf, int M)
{
    extern __shared__ char smem[];
    const uint32_t sb = smem_u32(smem);
    const int tid = threadIdx.x, wid = tid >> 5, lane = tid & 31;
    const int nw = wid & 3;          // 4 n-groups of 64
    const int mw = wid >> 2;         // 2 m-groups of 64
    const int b = blockIdx.z;
    const int n0 = blockIdx.x * 256;
    const int mtile = blockIdx.y * 128;
    constexpr int NCH = K >> 6;      // K-chunks of 64

    // ---- cp.async mapping: slot = tid&7 (16B), rbase = tid>>3 (0..31).
    // j=0..7 -> A rows rbase+32j (0..255); j=8..11 -> B rows rbase+32(j-8).
    const int slot = tid & 7;
    const int rbase = tid >> 3;
    const uint32_t swz = (uint32_t)(((rbase & 7) * 16)) ^ (uint32_t)(slot * 16);
    const __half* pa = X + ((size_t)b * NPIX + n0 + rbase) * K + slot * 8;
    const __half* pb = W + (size_t)(mtile + rbase) * K + slot * 8;

    auto load_chunk = [&](int c, int s) {
        const uint32_t st = sb + (uint32_t)s * STAGE_BYTES;
        const __half* sa = pa + (size_t)c * 64;
        const __half* sbp = pb + (size_t)c * 64;
#pragma unroll
        for (int j = 0; j < 8; j++)
            cp16(st + (uint32_t)(rbase + 32 * j) * 128 + swz, sa + (size_t)j * 32 * K);
#pragma unroll
        for (int j = 0; j < 4; j++)
            cp16(st + A_TILE_BYTES + (uint32_t)(rbase + 32 * j) * 128 + swz,
                 sbp + (size_t)j * 32 * K);
        cp_commit();
    };

    float acc[4][8][4];
#pragma unroll
    for (int i = 0; i < 4; i++)
#pragma unroll
        for (int j = 0; j < 8; j++)
#pragma unroll
            for (int q = 0; q < 4; q++) acc[i][j][q] = 0.f;

    const int l7 = lane & 7;
    const int mi = lane >> 3;
    const uint32_t lsw = (uint32_t)(l7 * 16);
    const int a_row_base = nw * 64 + (mi & 1) * 8 + l7;   // + nt*16
    const int a_colq = (mi >> 1);
    const int b_row_base = mw * 64 + (mi >> 1) * 8 + l7;  // + u*16
    const int b_colq = (mi & 1);

    uint32_t af[2][4][4], bf[2][4][4];

    auto load_frags = [&](uint32_t abase, uint32_t bbase, int s, int buf) {
#pragma unroll
        for (int nt = 0; nt < 4; nt++)
            ldm_x4(af[buf][nt], abase + (uint32_t)(a_row_base + nt * 16) * 128
                                 + (((uint32_t)(s * 2 + a_colq) * 16) ^ lsw));
#pragma unroll
        for (int u = 0; u < 4; u++)
            ldm_x4(bf[buf][u], bbase + (uint32_t)(b_row_base + u * 16) * 128
                                 + (((uint32_t)(s * 2 + b_colq) * 16) ^ lsw));
    };

    // prologue
    load_chunk(0, 0);
    load_chunk(1, 1);

#pragma unroll
    for (int c = 0; c < NCH; c++) {
        asm volatile("cp.async.wait_group 1;" ::: "memory");
        __syncthreads();

        if (c + 2 < NCH) load_chunk(c + 2, (c + 2) % NSTAGE);
        else             cp_commit();

        const uint32_t abase = sb + (uint32_t)(c % NSTAGE) * STAGE_BYTES;
        const uint32_t bbase = abase + A_TILE_BYTES;

        load_frags(abase, bbase, 0, 0);
#pragma unroll
        for (int s = 0; s < 4; s++) {
            const int cur = s & 1;
            if (s < 3) load_frags(abase, bbase, s + 1, cur ^ 1);
#pragma unroll
            for (int nt = 0; nt < 4; nt++)
#pragma unroll
                for (int u = 0; u < 4; u++) {
                    mma_f16(acc[nt][u * 2 + 0], af[cur][nt], bf[cur][u] + 0);
                    mma_f16(acc[nt][u * 2 + 1], af[cur][nt], bf[cur][u] + 2);
                }
        }
    }

    // -------- epilogue --------
    const int g = lane >> 2, tg = lane & 3;

    if (MODE == 0) {
#pragma unroll
        for (int nt = 0; nt < 4; nt++) {
            const int nloc = nw * 64 + nt * 16 + g;
            const size_t bn0 = (size_t)b * NPIX + n0 + nloc;
            const size_t bn1 = bn0 + 8;
#pragma unroll
            for (int u = 0; u < 4; u++)
#pragma unroll
                for (int h = 0; h < 2; h++) {
                    const int m = mtile + mw * 64 + u * 16 + h * 8 + tg * 2;
                    const float* cc = acc[nt][u * 2 + h];
                    const float b0 = bias[m], b1 = bias[m + 1];
                    __half2 p0, p1;
                    p0.x = __float2half_rn(fmaxf(cc[0] + b0, 0.f));
                    p0.y = __float2half_rn(fmaxf(cc[1] + b1, 0.f));
                    p1.x = __float2half_rn(fmaxf(cc[2] + b0, 0.f));
                    p1.y = __float2half_rn(fmaxf(cc[3] + b1, 0.f));
                    *(__half2*)(Oh + bn0 * M + m) = p0;
                    *(__half2*)(Oh + bn1 * M + m) = p1;
                }
        }
    } else {
        // fused pooling: Y3 tile -> smem, then p[k,c] = sum_n A[b,k,n]*Y[n,c]
        float* Ysm = (float*)(smem + YSM_OFF);
        float* As  = (float*)(smem + AS_OFF);
        __syncthreads();   // mainloop smem reads done before overlay writes
#pragma unroll
        for (int nt = 0; nt < 4; nt++) {
            const int nloc = nw * 64 + nt * 16 + g;
#pragma unroll
            for (int u = 0; u < 4; u++)
#pragma unroll
                for (int h = 0; h < 2; h++) {
                    const int m = mw * 64 + u * 16 + h * 8 + tg * 2;  // mtile==0 (M=128)
                    const float* cc = acc[nt][u * 2 + h];
                    const float b0 = bias[m], b1 = bias[m + 1];
                    *(float2*)(Ysm + (size_t)nloc * 128 + m) =
                        make_float2(fmaxf(cc[0] + b0, 0.f), fmaxf(cc[1] + b1, 0.f));
                    *(float2*)(Ysm + (size_t)(nloc + 8) * 128 + m) =
                        make_float2(fmaxf(cc[2] + b0, 0.f), fmaxf(cc[3] + b1, 0.f));
                }
        }
#pragma unroll
        for (int k = 0; k < NCLS; k++)
            As[k * 256 + tid] = g_A[(size_t)(b * NCLS + k) * NPIX + n0 + tid];
        __syncthreads();

        const int c = tid & 127;
        const int kh = (tid >> 7) * 4;   // classes kh..kh+3
        float p0 = 0.f, p1 = 0.f, p2 = 0.f, p3 = 0.f;
        for (int i = 0; i < 256; i++) {
            const float v = Ysm[(size_t)i * 128 + c];
            p0 = fmaf(As[(kh + 0) * 256 + i], v, p0);
            p1 = fmaf(As[(kh + 1) * 256 + i], v, p1);
            p2 = fmaf(As[(kh + 2) * 256 + i], v, p2);
            p3 = fmaf(As[(kh + 3) * 256 + i], v, p3);
        }
        float* dst = Pf + (((size_t)b * 25 + blockIdx.x) * NCLS + kh) * 128 + c;
        dst[0]   = p0;
        dst[128] = p1;
        dst[256] = p2;
        dst[384] = p3;
    }
}

// ---------------------------------------------------------------------------
__global__ void prep(const float* __restrict__ w1, const float* __restrict__ w2,
                     const float* __restrict__ w3) {
    int i = blockIdx.x * 256 + threadIdx.x;
    if (i < 512 * 256) g_w1[i] = __float2half_rn(w1[i]);
    if (i < 256 * 512) g_w2[i] = __float2half_rn(w2[i]);
    if (i < 128 * 256) g_w3[i] = __float2half_rn(w3[i]);
    if (i < NBATCH * NCLS * NPIX) g_A[i] = 0.f;
    if (i < NBATCH * NCLS) g_cnt[i] = 0.f;
}

// transpose feature [b][c][n] -> fp16 [b][n][256]
__global__ void transpose_feat(const float* __restrict__ f) {
    __shared__ float t[32][33];
    const int b = blockIdx.z, n0 = blockIdx.x * 32, c0 = blockIdx.y * 32;
    const int tx = threadIdx.x, ty = threadIdx.y;
    for (int i = ty; i < 32; i += 8)
        t[i][tx] = f[((size_t)b * 256 + c0 + i) * NPIX + n0 + tx];
    __syncthreads();
    for (int i = ty; i < 32; i += 8)
        g_XA[((size_t)b * NPIX + n0 + i) * 256 + c0 + tx] = __float2half_rn(t[tx][i]);
}

// ---------------------------------------------------------------------------
__global__ void label_kernel(const int* __restrict__ lbl) {
    __shared__ float cs[NCLS];
    const int tid = threadIdx.x;
    if (tid < NCLS) cs[tid] = 0.f;
    __syncthreads();
    const int idx = blockIdx.x * 256 + tid;
    const int Xo = idx % OUTP;
    const int t2 = idx / OUTP;
    const int Yo = t2 % OUTP;
    const int b = t2 / OUTP;
    const int k = lbl[idx];
    atomicAdd(&cs[k], 1.0f);

    const int my = Yo >> 1, mx = Xo >> 1;
    int jy0, jy1, jx0, jx1;
    float wy0, wy1, wx0, wx1;
    if ((Yo & 1) == 0) {
        jy0 = my - 1; wy0 = 0.25f; jy1 = my; wy1 = 0.75f;
        if (Yo == 0) { jy0 = 0; wy0 = 0.f; wy1 = 1.f; }
    } else {
        jy0 = my; wy0 = 0.75f; jy1 = my + 1; wy1 = 0.25f;
        if (Yo == OUTP - 1) { jy1 = INP - 1; wy1 = 0.f; wy0 = 1.f; }
    }
    if ((Xo & 1) == 0) {
        jx0 = mx - 1; wx0 = 0.25f; jx1 = mx; wx1 = 0.75f;
        if (Xo == 0) { jx0 = 0; wx0 = 0.f; wx1 = 1.f; }
    } else {
        jx0 = mx; wx0 = 0.75f; jx1 = mx + 1; wx1 = 0.25f;
        if (Xo == OUTP - 1) { jx1 = INP - 1; wx1 = 0.f; wx0 = 1.f; }
    }
    float* Ab = g_A + (size_t)(b * NCLS + k) * NPIX;
    float w;
    w = wy0 * wx0; if (w != 0.f) atomicAdd(&Ab[jy0 * INP + jx0], w);
    w = wy0 * wx1; if (w != 0.f) atomicAdd(&Ab[jy0 * INP + jx1], w);
    w = wy1 * wx0; if (w != 0.f) atomicAdd(&Ab[jy1 * INP + jx0], w);
    w = wy1 * wx1; if (w != 0.f) atomicAdd(&Ab[jy1 * INP + jx1], w);

    __syncthreads();
    if (tid < NCLS) atomicAdd(&g_cnt[b * NCLS + tid], cs[tid]);
}

// ---------------------------------------------------------------------------
__global__ void pool_final(float* __restrict__ out) {
    const int b = blockIdx.x;
    const int k = threadIdx.x >> 7, c = threadIdx.x & 127;
    float s = 0.f;
    for (int ch = 0; ch < 25; ch++)
        s += g_part[(((size_t)b * 25 + ch) * NCLS + k) * 128 + c];
    const float cv = g_cnt[b * NCLS + k];
    out[((size_t)b * NCLS + k) * 128 + c] = s / (cv + 1e-8f);
    if (c == 0) out[16384 + b * NCLS + k] = (cv > 0.f) ? 1.f : 0.f;
}

// ---------------------------------------------------------------------------
extern "C" void kernel_launch(void* const* d_in, const int* in_sizes, int n_in,
                              void* d_out, int out_size) {
    const float* feature = (const float*)d_in[0];
    const int*   label   = (const int*)d_in[1];
    const float* w1 = (const float*)d_in[2];
    const float* b1 = (const float*)d_in[3];
    const float* w2 = (const float*)d_in[4];
    const float* b2 = (const float*)d_in[5];
    const float* w3 = (const float*)d_in[6];
    const float* b3 = (const float*)d_in[7];
    float* out = (float*)d_out;

    void *xa, *xb, *w1d, *w2d, *w3d, *part;
    cudaGetSymbolAddress(&xa, g_XA);
    cudaGetSymbolAddress(&xb, g_XB);
    cudaGetSymbolAddress(&w1d, g_w1);
    cudaGetSymbolAddress(&w2d, g_w2);
    cudaGetSymbolAddress(&w3d, g_w3);
    cudaGetSymbolAddress(&part, g_part);

    cudaFuncSetAttribute(gemm_f16<256, 0>, cudaFuncAttributeMaxDynamicSharedMemorySize, SMEM_TOTAL);
    cudaFuncSetAttribute(gemm_f16<512, 0>, cudaFuncAttributeMaxDynamicSharedMemorySize, SMEM_TOTAL);
    cudaFuncSetAttribute(gemm_f16<256, 1>, cudaFuncAttributeMaxDynamicSharedMemorySize, SMEM_TOTAL);

    prep<<<3200, 256>>>(w1, w2, w3);
    transpose_feat<<<dim3(200, 8, 16), dim3(32, 8)>>>(feature);
    label_kernel<<<1600, 256>>>(label);

    // Y1 = relu(W1 Ft + b1): [b][n][512] fp16
    gemm_f16<256, 0><<<dim3(25, 4, 16), 256, SMEM_TOTAL>>>(
        (const __half*)xa, (const __half*)w1d, b1, (__half*)xb, nullptr, 512);
    // Y2 = relu(W2 Y1 + b2): [b][n][256] fp16
    gemm_f16<512, 0><<<dim3(25, 2, 16), 256, SMEM_TOTAL>>>(
        (const __half*)xb, (const __half*)w2d, b2, (__half*)xa, nullptr, 256);
    // Y3 = relu(W3 Y2 + b3) fused with masked pooling partials
    gemm_f16<256, 1><<<dim3(25, 1, 16), 256, SMEM_TOTAL>>>(
        (const __half*)xa, (const __half*)w3d, b3, nullptr, (float*)part, 128);

    pool_final<<<16, 1024>>>(out);
}